// round 15
// baseline (speedup 1.0000x reference)
#include <cuda_runtime.h>
#include <cuda_bf16.h>
#include <cstdint>

typedef __nv_bfloat16 bf16;
typedef __nv_bfloat162 bf162;

#define PCOLS 1360   // 1024 + 256 + 64 + 16 concatenated proj columns
#define LOG2E 1.4426950408889634f

// padded vocab sizes (multiples of 128)
#define VHP 20096    // head / tail1 padded (157*128)

// ---------------- device scratch (no cudaMalloc allowed) ----------------
__device__ __align__(16) bf16 g_Wh [(size_t)VHP * 1024];  // [W0 ; cluster_weight ; 0] * log2e
__device__ __align__(16) bf16 g_W1v[(size_t)VHP * 256];
__device__ __align__(16) bf16 g_hb [1024u * 1024];    // hidden bf16
__device__ __align__(16) bf16 g_pT [1360u * 1024];    // concat(p)^T  [n][k]
__device__ __align__(16) bf16 g_projb[1024u * PCOLS]; // proj bf16
__device__ __align__(4)  bf16 g_bbh[VHP];   // biases * log2e (bf16), pad = -30000
__device__ __align__(4)  bf16 g_bb1[VHP];
__device__ float g_partH[1024u * 157];    // [row][vtile] sum(2^logit')
__device__ float g_part1[1024u * 157];
__device__ float g_part2[1024u * 1250];
__device__ float g_part3[1024u * 530];

// ---------------- helpers ----------------
__device__ __forceinline__ void ldsm_x4(unsigned r[4], const bf16* p) {
    unsigned a = (unsigned)__cvta_generic_to_shared((const void*)p);
    asm volatile("ldmatrix.sync.aligned.m8n8.x4.shared.b16 {%0,%1,%2,%3}, [%4];"
                 : "=r"(r[0]), "=r"(r[1]), "=r"(r[2]), "=r"(r[3]) : "r"(a));
}
__device__ __forceinline__ void mma16816(float c[4], const unsigned a[4], const unsigned b[2]) {
    asm volatile("mma.sync.aligned.m16n8k16.row.col.f32.bf16.bf16.f32 "
                 "{%0,%1,%2,%3}, {%4,%5,%6,%7}, {%8,%9}, {%0,%1,%2,%3};"
                 : "+f"(c[0]), "+f"(c[1]), "+f"(c[2]), "+f"(c[3])
                 : "r"(a[0]), "r"(a[1]), "r"(a[2]), "r"(a[3]), "r"(b[0]), "r"(b[1]));
}
__device__ __forceinline__ void cpa16(bf16* dst, const bf16* src) {
    unsigned d = (unsigned)__cvta_generic_to_shared((void*)dst);
    asm volatile("cp.async.cg.shared.global [%0], [%1], 16;" :: "r"(d), "l"(src));
}
#define CP_COMMIT() asm volatile("cp.async.commit_group;")

#define GS(i,n) for (size_t i = blockIdx.x*(size_t)blockDim.x + threadIdx.x; i < (size_t)(n); i += (size_t)gridDim.x*blockDim.x)

__device__ __forceinline__ uint4 pack8_scaled(float4 a, float4 b) {
    bf162 x0 = __floats2bfloat162_rn(a.x * LOG2E, a.y * LOG2E);
    bf162 x1 = __floats2bfloat162_rn(a.z * LOG2E, a.w * LOG2E);
    bf162 x2 = __floats2bfloat162_rn(b.x * LOG2E, b.y * LOG2E);
    bf162 x3 = __floats2bfloat162_rn(b.z * LOG2E, b.w * LOG2E);
    uint4 o;
    o.x = *(unsigned*)&x0; o.y = *(unsigned*)&x1;
    o.z = *(unsigned*)&x2; o.w = *(unsigned*)&x3;
    return o;
}

// ---------------- conversion kernels ----------------
__global__ void k_convHP(const float4* __restrict__ h,
                         const float* __restrict__ p0, const float* __restrict__ p1,
                         const float* __restrict__ p2, const float* __restrict__ p3) {
    if (blockIdx.x < 512) {
        size_t u = blockIdx.x * 256u + threadIdx.x;
        float4 a = h[2 * u], b = h[2 * u + 1];
        bf162 x0 = __floats2bfloat162_rn(a.x, a.y);
        bf162 x1 = __floats2bfloat162_rn(a.z, a.w);
        bf162 x2 = __floats2bfloat162_rn(b.x, b.y);
        bf162 x3 = __floats2bfloat162_rn(b.z, b.w);
        uint4 o;
        o.x = *(unsigned*)&x0; o.y = *(unsigned*)&x1;
        o.z = *(unsigned*)&x2; o.w = *(unsigned*)&x3;
        ((uint4*)g_hb)[u] = o;
    } else {
        __shared__ float tile[32][33];
        int b = blockIdx.x - 512;
        int nb = (b % 43) * 32, rb = (b / 43) * 32;
        int tx = threadIdx.x & 31, ty = threadIdx.x >> 5;
#pragma unroll
        for (int yy = 0; yy < 32; yy += 8) {
            int r = rb + ty + yy, n = nb + tx;
            float v = 0.f;
            if (n < PCOLS) {
                if      (n < 1024) v = p0[(size_t)r * 1024 + n];
                else if (n < 1280) v = p1[(size_t)r * 256  + (n - 1024)];
                else if (n < 1344) v = p2[(size_t)r * 64   + (n - 1280)];
                else               v = p3[(size_t)r * 16   + (n - 1344)];
            }
            tile[ty + yy][tx] = v;
        }
        __syncthreads();
#pragma unroll
        for (int yy = 0; yy < 32; yy += 8) {
            int n = nb + ty + yy, r = rb + tx;
            if (n < PCOLS) g_pT[(size_t)n * 1024 + r] = __float2bfloat16(tile[tx][ty + yy]);
        }
    }
}

__global__ void k_convHead(const float4* __restrict__ W0, const float4* __restrict__ cw,
                           const float* __restrict__ b0, const float* __restrict__ cb) {
    const size_t u0 = 19997u * 1024 / 8, u1 = 20000u * 1024 / 8;
    GS(i, (size_t)VHP * 1024 / 8) {
        float4 a, b;
        if (i < u0)      { a = W0[2 * i]; b = W0[2 * i + 1]; }
        else if (i < u1) { a = cw[2 * (i - u0)]; b = cw[2 * (i - u0) + 1]; }
        else             { a = b = make_float4(0.f, 0.f, 0.f, 0.f); }
        ((uint4*)g_Wh)[i] = pack8_scaled(a, b);
        if (i < VHP) {
            float bb = (i < 19997) ? b0[i] * LOG2E
                     : (i < 20000) ? cb[i - 19997] * LOG2E : -30000.f;
            g_bbh[i] = __float2bfloat16(bb);
        }
    }
}

__global__ void k_convW1(const float4* __restrict__ W1, const float* __restrict__ b1) {
    const size_t r1 = 20000u * 256 / 8;
    GS(i, (size_t)VHP * 256 / 8) {
        float4 a, b;
        if (i < r1) { a = W1[2 * i]; b = W1[2 * i + 1]; }
        else        { a = b = make_float4(0.f, 0.f, 0.f, 0.f); }
        ((uint4*)g_W1v)[i] = pack8_scaled(a, b);
        if (i < VHP) g_bb1[i] = __float2bfloat16(i < 20000 ? b1[i] * LOG2E : -30000.f);
    }
}

// ---------------- proj GEMM (3-stage pipelined): g_projb = g_hb @ g_pT^T ----------------
__global__ __launch_bounds__(256, 2)
void gemm_proj() {
    constexpr int BK = 64, LD = BK + 8, T = 16, R8 = BK / 8, BUF = 128 * LD, STG = 2 * BUF;
    extern __shared__ bf16 smem[];
    const int tid = threadIdx.x, warp = tid >> 5, lane = tid & 31;
    const int wm = warp >> 1, wn = warp & 1;
    const int nbase = blockIdx.x * 128, rb = blockIdx.y;
    float acc[2][8][4];
#pragma unroll
    for (int a = 0; a < 2; a++)
#pragma unroll
        for (int b = 0; b < 8; b++)
#pragma unroll
            for (int c = 0; c < 4; c++) acc[a][b][c] = 0.f;

    auto load = [&](int kt) {
        bf16* s = smem + (kt % 3) * STG;
        const bf16* As = g_hb + (size_t)(rb * 128) * 1024 + kt * BK;
        const bf16* Bs = g_pT + kt * BK;
#pragma unroll
        for (int i = tid; i < 128 * R8; i += 256) {
            int r = i / R8, c = i % R8;
            cpa16(s + r * LD + c * 8, As + (size_t)r * 1024 + c * 8);
            int wr = (nbase + r < PCOLS) ? nbase + r : PCOLS - 1;
            cpa16(s + BUF + r * LD + c * 8, Bs + (size_t)wr * 1024 + c * 8);
        }
        CP_COMMIT();
    };
    load(0); load(1);
    for (int kt = 0; kt < T; kt++) {
        if (kt < T - 1) asm volatile("cp.async.wait_group 1;");
        else            asm volatile("cp.async.wait_group 0;");
        __syncthreads();
        if (kt + 2 < T) load(kt + 2);
        const bf16* aB = smem + (kt % 3) * STG;
        const bf16* bB = aB + BUF;
#pragma unroll
        for (int ks = 0; ks < BK / 16; ks++) {
            unsigned afr[2][4];
#pragma unroll
            for (int mt = 0; mt < 2; mt++)
                ldsm_x4(afr[mt], aB + (wm * 32 + mt * 16 + (lane & 15)) * LD + ks * 16 + (lane >> 4) * 8);
#pragma unroll
            for (int np = 0; np < 4; np++) {
                unsigned bq[4];
                int g = lane >> 3;
                ldsm_x4(bq, bB + (wn * 64 + (np * 2 + (g >> 1)) * 8 + (lane & 7)) * LD + ks * 16 + (g & 1) * 8);
                mma16816(acc[0][np * 2],     afr[0], bq);
                mma16816(acc[1][np * 2],     afr[1], bq);
                mma16816(acc[0][np * 2 + 1], afr[0], bq + 2);
                mma16816(acc[1][np * 2 + 1], afr[1], bq + 2);
            }
        }
    }
#pragma unroll
    for (int mt = 0; mt < 2; mt++)
#pragma unroll
        for (int nt = 0; nt < 8; nt++)
#pragma unroll
            for (int k = 0; k < 4; k++) {
                int r = rb * 128 + wm * 32 + mt * 16 + (lane >> 2) + ((k >= 2) ? 8 : 0);
                int c = nbase + wn * 64 + nt * 8 + (lane & 3) * 2 + (k & 1);
                if (c < PCOLS) g_projb[(size_t)r * PCOLS + c] = __float2bfloat16(acc[mt][nt][k]);
            }
}

// ---------------- persistent fused GEMM + sum(2^x): head (K=1024) / tail1 (K=256) ----------------
// Grid = 296 CTAs; each CTA processes tiles t = bid + 296*i of the 157x8 = 1256 tile space.
// Continuous 3-stage cp.async ring across tile boundaries (empty commit groups keep
// wait_group arithmetic uniform). Epilogue at each tile's last K-chunk.
template <int K>
__global__ __launch_bounds__(256, 2)
void gemm_lse_pers(int id, int proj_off) {
    constexpr int BK = 64, LD = BK + 8, T = K / BK, R8 = BK / 8, BUF = 128 * LD, STG = 2 * BUF;
    constexpr int NTILES = 1256, NT = 157;
    extern __shared__ bf16 smem[];
    float* sRf = (float*)(smem + 3 * STG);

    const bf16* Wb = (id == 0) ? g_Wh  : g_W1v;
    const bf16* bb = (id == 0) ? g_bbh : g_bb1;
    float* part    = (id == 0) ? g_partH : g_part1;

    const int tid = threadIdx.x, warp = tid >> 5, lane = tid & 31;
    const int wm = warp >> 1, wn = warp & 1;
    const int bid = blockIdx.x;
    const int myTiles = (NTILES - bid + 295) / 296;
    const int NCH = myTiles * T;

    auto load = [&](int c) {
        if (c < NCH) {
            int i = c / T, kt = c - i * T;
            int tile = bid + 296 * i;
            int vt = tile % NT, rb = tile / NT;
            const bf16* As = g_projb + (size_t)(rb * 128) * PCOLS + proj_off + kt * BK;
            const bf16* Bs = Wb + (size_t)(vt * 128) * K + kt * BK;
            bf16* s = smem + (c % 3) * STG;
#pragma unroll
            for (int u = tid; u < 128 * R8; u += 256) {
                int r = u / R8, cc = u % R8;
                cpa16(s + r * LD + cc * 8, As + (size_t)r * PCOLS + cc * 8);
                cpa16(s + BUF + r * LD + cc * 8, Bs + (size_t)r * K + cc * 8);
            }
        }
        CP_COMMIT();
    };

    float acc[2][8][4];
#pragma unroll
    for (int a = 0; a < 2; a++)
#pragma unroll
        for (int b = 0; b < 8; b++)
#pragma unroll
            for (int c = 0; c < 4; c++) acc[a][b][c] = 0.f;

    load(0); load(1);
    for (int c = 0; c < NCH; c++) {
        asm volatile("cp.async.wait_group 1;");
        __syncthreads();
        load(c + 2);
        const bf16* aB = smem + (c % 3) * STG;
        const bf16* bB = aB + BUF;
#pragma unroll
        for (int ks = 0; ks < BK / 16; ks++) {
            unsigned afr[2][4];
#pragma unroll
            for (int mt = 0; mt < 2; mt++)
                ldsm_x4(afr[mt], aB + (wm * 32 + mt * 16 + (lane & 15)) * LD + ks * 16 + (lane >> 4) * 8);
#pragma unroll
            for (int np = 0; np < 4; np++) {
                unsigned bq[4];
                int g = lane >> 3;
                ldsm_x4(bq, bB + (wn * 64 + (np * 2 + (g >> 1)) * 8 + (lane & 7)) * LD + ks * 16 + (g & 1) * 8);
                mma16816(acc[0][np * 2],     afr[0], bq);
                mma16816(acc[1][np * 2],     afr[1], bq);
                mma16816(acc[0][np * 2 + 1], afr[0], bq + 2);
                mma16816(acc[1][np * 2 + 1], afr[1], bq + 2);
            }
        }
        if ((c % T) == T - 1) {
            // epilogue for finished tile
            int tile = bid + 296 * (c / T);
            int vt = tile % NT, rb = tile / NT;
            int vbase = vt * 128;
            unsigned bpre[8];
#pragma unroll
            for (int nt = 0; nt < 8; nt++)
                bpre[nt] = *(const unsigned*)(bb + (vbase + wn * 64 + nt * 8 + (lane & 3) * 2));
#pragma unroll
            for (int mt = 0; mt < 2; mt++)
#pragma unroll
                for (int rr = 0; rr < 2; rr++) {
                    float s0 = 0.f, s1 = 0.f;
#pragma unroll
                    for (int nt = 0; nt < 8; nt++) {
                        float a0 = acc[mt][nt][rr * 2], a1 = acc[mt][nt][rr * 2 + 1];
                        unsigned lp, lb, e;
                        asm("cvt.rn.bf16x2.f32 %0, %1, %2;" : "=r"(lp) : "f"(a1), "f"(a0));
                        asm("fma.rn.bf16x2 %0, %1, %2, %3;" : "=r"(lb) : "r"(lp), "r"(0x3F803F80u), "r"(bpre[nt]));
                        asm("ex2.approx.ftz.bf16x2 %0, %1;" : "=r"(e) : "r"(lb));
                        s0 += __uint_as_float(e << 16);
                        s1 += __uint_as_float(e & 0xFFFF0000u);
                    }
                    float s = s0 + s1;
                    s += __shfl_xor_sync(0xffffffffu, s, 1);
                    s += __shfl_xor_sync(0xffffffffu, s, 2);
                    if ((lane & 3) == 0)
                        sRf[(wm * 32 + mt * 16 + rr * 8 + (lane >> 2)) * 2 + wn] = s;
                }
            __syncthreads();
            if (tid < 128)
                part[(size_t)(rb * 128 + tid) * NT + vt] = sRf[tid * 2] + sRf[tid * 2 + 1];
            // reset accumulators for next tile
#pragma unroll
            for (int a = 0; a < 2; a++)
#pragma unroll
                for (int b = 0; b < 8; b++)
#pragma unroll
                    for (int k = 0; k < 4; k++) acc[a][b][k] = 0.f;
        }
    }
}

// ---------------- tail GEMM+LSE: fp32 W converted in-kernel, B resident (K = 64 / 16) ----------------
template <int K>
__global__ __launch_bounds__(256, 2)
void gemm_lse_tail(const float* __restrict__ W, const float* __restrict__ bias,
                   int proj_off, int NT, int V) {
    constexpr int LD = K + 8, R8 = K / 8, ABUF = 128 * LD;
    extern __shared__ bf16 smem[];
    bf16* sA = smem;               // 2 buffers
    bf16* sB = smem + 2 * ABUF;    // resident B (converted from fp32 here)
    float* sRf = (float*)(smem + 3 * ABUF);
    float* part = (K == 64) ? g_part2 : g_part3;

    const int tid = threadIdx.x, warp = tid >> 5, lane = tid & 31;
    const int wm = warp >> 1, wn = warp & 1;
    const int vt = blockIdx.x;
    const int vbase = vt * 128;

    // bias: load fp32, scale, pack to bf16x2 (pad -> -30000 => 2^x = 0)
    unsigned bpre[8];
#pragma unroll
    for (int nt = 0; nt < 8; nt++) {
        int col = vbase + wn * 64 + nt * 8 + (lane & 3) * 2;
        float f0 = (col     < V) ? bias[col]     * LOG2E : -30000.f;
        float f1 = (col + 1 < V) ? bias[col + 1] * LOG2E : -30000.f;
        bf162 p = __floats2bfloat162_rn(f0, f1);
        bpre[nt] = *(unsigned*)&p;
    }

    // A(rb=0) via cp.async
    {
        const bf16* As = g_projb + proj_off;
#pragma unroll
        for (int i = tid; i < 128 * R8; i += 256) {
            int r = i / R8, c = i % R8;
            cpa16(sA + r * LD + c * 8, As + (size_t)r * PCOLS + c * 8);
        }
        CP_COMMIT();
    }
    // resident B: fp32 -> bf16*log2e, direct from input weights (read exactly once)
    {
        constexpr int UN = 128 * K / 8;   // 8-element units
#pragma unroll
        for (int u = tid; u < UN; u += 256) {
            int r = u / (K / 8), cc = u % (K / 8);
            int row = vbase + r; if (row >= V) row = V - 1;
            const float4* Wf = (const float4*)(W + (size_t)row * K + cc * 8);
            *(uint4*)(sB + r * LD + cc * 8) = pack8_scaled(Wf[0], Wf[1]);
        }
    }
    for (int rb = 0; rb < 8; rb++) {
        int buf = rb & 1;
        if (rb + 1 < 8) {
            const bf16* As = g_projb + (size_t)((rb + 1) * 128) * PCOLS + proj_off;
#pragma unroll
            for (int i = tid; i < 128 * R8; i += 256) {
                int r = i / R8, c = i % R8;
                cpa16(sA + (buf ^ 1) * ABUF + r * LD + c * 8, As + (size_t)r * PCOLS + c * 8);
            }
            CP_COMMIT();
            asm volatile("cp.async.wait_group 1;");
        } else {
            asm volatile("cp.async.wait_group 0;");
        }
        __syncthreads();
        const bf16* aB = sA + buf * ABUF;
        float acc[2][8][4];
#pragma unroll
        for (int a = 0; a < 2; a++)
#pragma unroll
            for (int b = 0; b < 8; b++)
#pragma unroll
                for (int c = 0; c < 4; c++) acc[a][b][c] = 0.f;
#pragma unroll
        for (int ks = 0; ks < K / 16; ks++) {
            unsigned afr[2][4];
#pragma unroll
            for (int mt = 0; mt < 2; mt++)
                ldsm_x4(afr[mt], aB + (wm * 32 + mt * 16 + (lane & 15)) * LD + ks * 16 + (lane >> 4) * 8);
#pragma unroll
            for (int np = 0; np < 4; np++) {
                unsigned bq[4];
                int g = lane >> 3;
                ldsm_x4(bq, sB + (wn * 64 + (np * 2 + (g >> 1)) * 8 + (lane & 7)) * LD + ks * 16 + (g & 1) * 8);
                mma16816(acc[0][np * 2],     afr[0], bq);
                mma16816(acc[1][np * 2],     afr[1], bq);
                mma16816(acc[0][np * 2 + 1], afr[0], bq + 2);
                mma16816(acc[1][np * 2 + 1], afr[1], bq + 2);
            }
        }
#pragma unroll
        for (int mt = 0; mt < 2; mt++)
#pragma unroll
            for (int rr = 0; rr < 2; rr++) {
                float s0 = 0.f, s1 = 0.f;
#pragma unroll
                for (int nt = 0; nt < 8; nt++) {
                    float a0 = acc[mt][nt][rr * 2], a1 = acc[mt][nt][rr * 2 + 1];
                    unsigned lp, lb, e;
                    asm("cvt.rn.bf16x2.f32 %0, %1, %2;" : "=r"(lp) : "f"(a1), "f"(a0));
                    asm("fma.rn.bf16x2 %0, %1, %2, %3;" : "=r"(lb) : "r"(lp), "r"(0x3F803F80u), "r"(bpre[nt]));
                    asm("ex2.approx.ftz.bf16x2 %0, %1;" : "=r"(e) : "r"(lb));
                    s0 += __uint_as_float(e << 16);
                    s1 += __uint_as_float(e & 0xFFFF0000u);
                }
                float s = s0 + s1;
                s += __shfl_xor_sync(0xffffffffu, s, 1);
                s += __shfl_xor_sync(0xffffffffu, s, 2);
                if ((lane & 3) == 0)
                    sRf[(wm * 32 + mt * 16 + rr * 8 + (lane >> 2)) * 2 + wn] = s;
            }
        __syncthreads();
        if (tid < 128)
            part[(size_t)(rb * 128 + tid) * NT + vt] = sRf[tid * 2] + sRf[tid * 2 + 1];
        __syncthreads();
    }
}

// ---------------- final: combine partials + target logits ----------------
__device__ __forceinline__ float warp_sum(float x) {
#pragma unroll
    for (int d = 16; d; d >>= 1) x += __shfl_xor_sync(0xffffffffu, x, d);
    return x;
}
__device__ __forceinline__ float warp_lse(const float* part, int nt, int row, int lane) {
    float s = 0.f;
    for (int i = lane; i < nt; i += 32) s += part[(size_t)row * nt + i];
    return __logf(warp_sum(s));
}

__global__ __launch_bounds__(256)
void final_kernel(const unsigned* __restrict__ tgt,
                  const float* __restrict__ W0, const float* __restrict__ b0,
                  const float* __restrict__ W1, const float* __restrict__ b1,
                  const float* __restrict__ W2, const float* __restrict__ b2,
                  const float* __restrict__ W3, const float* __restrict__ b3,
                  const float* __restrict__ cw, const float* __restrict__ cb,
                  float* __restrict__ out) {
    const int warp = threadIdx.x >> 5, lane = threadIdx.x & 31;
    const int row = blockIdx.x * 8 + warp;
    if (row >= 1024) return;
    unsigned odd = tgt[1] | tgt[3] | tgt[5] | tgt[7] | tgt[9] | tgt[11] | tgt[13] | tgt[15];
    bool is64 = (odd == 0u);
    int t = (int)(is64 ? tgt[2 * row] : tgt[row]);

    float lseH = warp_lse(g_partH, 157, row, lane);
    const bf16* pr = g_projb + (size_t)row * PCOLS;
    float nll;
    if (t < 19997) {
        float d = 0.f;
        for (int k = lane; k < 1024; k += 32)
            d += __bfloat162float(pr[k]) * W0[(size_t)t * 1024 + k];
        d = warp_sum(d);
        nll = lseH - (d + b0[t]);
    } else {
        int ci, loff, Kc, ntc, poff;
        const float *Wt, *bt;
        const float* part;
        if (t < 39997)       { ci = 0; loff = 19997;  Kc = 256; ntc = 157;  poff = 1024; Wt = W1; bt = b1; part = g_part1; }
        else if (t < 199997) { ci = 1; loff = 39997;  Kc = 64;  ntc = 1250; poff = 1280; Wt = W2; bt = b2; part = g_part2; }
        else                 { ci = 2; loff = 199997; Kc = 16;  ntc = 530;  poff = 1344; Wt = W3; bt = b3; part = g_part3; }
        float lseT = warp_lse(part, ntc, row, lane);
        float dc = 0.f;
        for (int k = lane; k < 1024; k += 32)
            dc += __bfloat162float(pr[k]) * cw[(size_t)ci * 1024 + k];
        dc = warp_sum(dc);
        int rel = t - loff;
        float dt = 0.f;
        for (int k = lane; k < Kc; k += 32)
            dt += __bfloat162float(pr[poff + k]) * Wt[(size_t)rel * Kc + k];
        dt = warp_sum(dt);
        nll = (lseH - (dc + cb[ci])) + (lseT - (dt + bt[rel]));
    }
    if (lane == 0) out[row] = nll;
}

// ---------------- launch (multi-stream overlap, graph-capture safe) ----------------
struct AuxStreams {
    cudaStream_t s1, s2;
    cudaEvent_t eRoot, eHead, eW1, eProj, eSide;
    AuxStreams() {
        cudaStreamCreateWithFlags(&s1, cudaStreamNonBlocking);
        cudaStreamCreateWithFlags(&s2, cudaStreamNonBlocking);
        cudaEventCreateWithFlags(&eRoot, cudaEventDisableTiming);
        cudaEventCreateWithFlags(&eHead, cudaEventDisableTiming);
        cudaEventCreateWithFlags(&eW1,   cudaEventDisableTiming);
        cudaEventCreateWithFlags(&eProj, cudaEventDisableTiming);
        cudaEventCreateWithFlags(&eSide, cudaEventDisableTiming);
    }
};
static AuxStreams& aux() { static AuxStreams a; return a; }

extern "C" void kernel_launch(void* const* d_in, const int* in_sizes, int n_in,
                              void* d_out, int out_size) {
    const float*    hidden = (const float*)d_in[0];
    const unsigned* target = (const unsigned*)d_in[1];
    const float* W0 = (const float*)d_in[2],  *b0 = (const float*)d_in[3],  *p0 = (const float*)d_in[4];
    const float* W1 = (const float*)d_in[5],  *b1 = (const float*)d_in[6],  *p1 = (const float*)d_in[7];
    const float* W2 = (const float*)d_in[8],  *b2 = (const float*)d_in[9],  *p2 = (const float*)d_in[10];
    const float* W3 = (const float*)d_in[11], *b3 = (const float*)d_in[12], *p3 = (const float*)d_in[13];
    const float* cw = (const float*)d_in[14], *cb = (const float*)d_in[15];
    float* out = (float*)d_out;
    AuxStreams& ax = aux();

    const int SM3   = 3 * (2 * 128 * 72) * 2 + 1024;    // 111616 B (3 stages A+B, + sRf)
    const int SMPJ  = 3 * (2 * 128 * 72) * 2;           // 110592 B
    const int SMT64 = 3 * 128 * 72 * 2 + 128 * 2 * 4;   // 56320 B
    const int SMT16 = 3 * 128 * 24 * 2 + 128 * 2 * 4;   // 19456 B
    cudaFuncSetAttribute(gemm_proj,          cudaFuncAttributeMaxDynamicSharedMemorySize, SMPJ);
    cudaFuncSetAttribute(gemm_lse_pers<1024>,cudaFuncAttributeMaxDynamicSharedMemorySize, SM3);
    cudaFuncSetAttribute(gemm_lse_pers<256>, cudaFuncAttributeMaxDynamicSharedMemorySize, SM3);
    cudaFuncSetAttribute(gemm_lse_tail<64>,  cudaFuncAttributeMaxDynamicSharedMemorySize, SMT64);
    cudaFuncSetAttribute(gemm_lse_tail<16>,  cudaFuncAttributeMaxDynamicSharedMemorySize, SMT16);

    cudaEventRecord(ax.eRoot, 0);

    // main stream: hidden/proj conversion -> proj GEMM
    k_convHP<<<1888, 256>>>((const float4*)hidden, p0, p1, p2, p3);                    // #0
    // side stream 1: head weight conversion (overlaps convHP + proj)
    cudaStreamWaitEvent(ax.s1, ax.eRoot, 0);
    k_convHead<<<8192, 256, 0, ax.s1>>>((const float4*)W0, (const float4*)cw, b0, cb); // #1
    cudaEventRecord(ax.eHead, ax.s1);

    gemm_proj<<<dim3(11, 8), 256, SMPJ>>>();                                           // #2
    cudaEventRecord(ax.eProj, 0);

    // head GEMM (needs convHead + proj), persistent grid
    cudaStreamWaitEvent(0, ax.eHead, 0);
    gemm_lse_pers<1024><<<296, 256, SM3>>>(0, 0);                                      // #3 <- profile me

    // side stream 2: W1 conversion; tail2/3 need only proj (W2/W3 converted in-kernel)
    cudaStreamWaitEvent(ax.s2, ax.eRoot, 0);
    k_convW1<<<2560, 256, 0, ax.s2>>>((const float4*)W1, b1);                          // #4
    cudaEventRecord(ax.eW1, ax.s2);
    cudaStreamWaitEvent(ax.s2, ax.eProj, 0);
    gemm_lse_tail<64><<<1250, 256, SMT64, ax.s2>>>(W2, b2, 1280, 1250, 160000);        // #5
    gemm_lse_tail<16><<<530,  256, SMT16, ax.s2>>>(W3, b3, 1344, 530, 67738);          // #6
    cudaEventRecord(ax.eSide, ax.s2);

    // main stream: tail1 GEMM (needs convW1), then final join
    cudaStreamWaitEvent(0, ax.eW1, 0);
    gemm_lse_pers<256><<<296, 256, SM3>>>(1, 1024);                                    // #7
    cudaStreamWaitEvent(0, ax.eSide, 0);
    final_kernel<<<128, 256>>>(target, W0, b0, W1, b1, W2, b2, W3, b3, cw, cb, out);   // #8
}

// round 17
// speedup vs baseline: 1.0931x; 1.0931x over previous
#include <cuda_runtime.h>
#include <cuda_bf16.h>
#include <cstdint>

typedef __nv_bfloat16 bf16;
typedef __nv_bfloat162 bf162;

#define PCOLS 1360   // 1024 + 256 + 64 + 16 concatenated proj columns
#define LOG2E 1.4426950408889634f

// padded vocab sizes (multiples of 128)
#define VHP 20096    // head / tail1 padded (157*128)

// ---------------- device scratch (no cudaMalloc allowed) ----------------
__device__ __align__(16) bf16 g_Wh [(size_t)VHP * 1024];  // [W0 ; cluster_weight ; 0] * log2e
__device__ __align__(16) bf16 g_W1v[(size_t)VHP * 256];
__device__ __align__(16) bf16 g_hb [1024u * 1024];    // hidden bf16
__device__ __align__(16) bf16 g_pT [1360u * 1024];    // concat(p)^T  [n][k]
__device__ __align__(16) bf16 g_projb[1024u * PCOLS]; // proj bf16
__device__ __align__(4)  bf16 g_bbh[VHP];   // biases * log2e (bf16), pad = -30000
__device__ __align__(4)  bf16 g_bb1[VHP];
__device__ float g_partH[1024u * 157];    // [row][vtile] sum(2^logit')
__device__ float g_part1[1024u * 157];
__device__ float g_part2[1024u * 1250];
__device__ float g_part3[1024u * 530];

// ---------------- helpers ----------------
__device__ __forceinline__ void ldsm_x4(unsigned r[4], const bf16* p) {
    unsigned a = (unsigned)__cvta_generic_to_shared((const void*)p);
    asm volatile("ldmatrix.sync.aligned.m8n8.x4.shared.b16 {%0,%1,%2,%3}, [%4];"
                 : "=r"(r[0]), "=r"(r[1]), "=r"(r[2]), "=r"(r[3]) : "r"(a));
}
__device__ __forceinline__ void mma16816(float c[4], const unsigned a[4], const unsigned b[2]) {
    asm volatile("mma.sync.aligned.m16n8k16.row.col.f32.bf16.bf16.f32 "
                 "{%0,%1,%2,%3}, {%4,%5,%6,%7}, {%8,%9}, {%0,%1,%2,%3};"
                 : "+f"(c[0]), "+f"(c[1]), "+f"(c[2]), "+f"(c[3])
                 : "r"(a[0]), "r"(a[1]), "r"(a[2]), "r"(a[3]), "r"(b[0]), "r"(b[1]));
}
__device__ __forceinline__ void cpa16(bf16* dst, const bf16* src) {
    unsigned d = (unsigned)__cvta_generic_to_shared((void*)dst);
    asm volatile("cp.async.cg.shared.global [%0], [%1], 16;" :: "r"(d), "l"(src));
}
#define CP_COMMIT() asm volatile("cp.async.commit_group;")

#define GS(i,n) for (size_t i = blockIdx.x*(size_t)blockDim.x + threadIdx.x; i < (size_t)(n); i += (size_t)gridDim.x*blockDim.x)

__device__ __forceinline__ uint4 pack8_scaled(float4 a, float4 b) {
    bf162 x0 = __floats2bfloat162_rn(a.x * LOG2E, a.y * LOG2E);
    bf162 x1 = __floats2bfloat162_rn(a.z * LOG2E, a.w * LOG2E);
    bf162 x2 = __floats2bfloat162_rn(b.x * LOG2E, b.y * LOG2E);
    bf162 x3 = __floats2bfloat162_rn(b.z * LOG2E, b.w * LOG2E);
    uint4 o;
    o.x = *(unsigned*)&x0; o.y = *(unsigned*)&x1;
    o.z = *(unsigned*)&x2; o.w = *(unsigned*)&x3;
    return o;
}

// ---------------- conversion kernels ----------------
__global__ void k_convHP(const float4* __restrict__ h,
                         const float* __restrict__ p0, const float* __restrict__ p1,
                         const float* __restrict__ p2, const float* __restrict__ p3) {
    if (blockIdx.x < 512) {
        size_t u = blockIdx.x * 256u + threadIdx.x;
        float4 a = h[2 * u], b = h[2 * u + 1];
        bf162 x0 = __floats2bfloat162_rn(a.x, a.y);
        bf162 x1 = __floats2bfloat162_rn(a.z, a.w);
        bf162 x2 = __floats2bfloat162_rn(b.x, b.y);
        bf162 x3 = __floats2bfloat162_rn(b.z, b.w);
        uint4 o;
        o.x = *(unsigned*)&x0; o.y = *(unsigned*)&x1;
        o.z = *(unsigned*)&x2; o.w = *(unsigned*)&x3;
        ((uint4*)g_hb)[u] = o;
    } else {
        __shared__ float tile[32][33];
        int b = blockIdx.x - 512;
        int nb = (b % 43) * 32, rb = (b / 43) * 32;
        int tx = threadIdx.x & 31, ty = threadIdx.x >> 5;
#pragma unroll
        for (int yy = 0; yy < 32; yy += 8) {
            int r = rb + ty + yy, n = nb + tx;
            float v = 0.f;
            if (n < PCOLS) {
                if      (n < 1024) v = p0[(size_t)r * 1024 + n];
                else if (n < 1280) v = p1[(size_t)r * 256  + (n - 1024)];
                else if (n < 1344) v = p2[(size_t)r * 64   + (n - 1280)];
                else               v = p3[(size_t)r * 16   + (n - 1344)];
            }
            tile[ty + yy][tx] = v;
        }
        __syncthreads();
#pragma unroll
        for (int yy = 0; yy < 32; yy += 8) {
            int n = nb + ty + yy, r = rb + tx;
            if (n < PCOLS) g_pT[(size_t)n * 1024 + r] = __float2bfloat16(tile[tx][ty + yy]);
        }
    }
}

__global__ void k_convHead(const float4* __restrict__ W0, const float4* __restrict__ cw,
                           const float* __restrict__ b0, const float* __restrict__ cb) {
    const size_t u0 = 19997u * 1024 / 8, u1 = 20000u * 1024 / 8;
    GS(i, (size_t)VHP * 1024 / 8) {
        float4 a, b;
        if (i < u0)      { a = W0[2 * i]; b = W0[2 * i + 1]; }
        else if (i < u1) { a = cw[2 * (i - u0)]; b = cw[2 * (i - u0) + 1]; }
        else             { a = b = make_float4(0.f, 0.f, 0.f, 0.f); }
        ((uint4*)g_Wh)[i] = pack8_scaled(a, b);
        if (i < VHP) {
            float bb = (i < 19997) ? b0[i] * LOG2E
                     : (i < 20000) ? cb[i - 19997] * LOG2E : -30000.f;
            g_bbh[i] = __float2bfloat16(bb);
        }
    }
}

__global__ void k_convW1(const float4* __restrict__ W1, const float* __restrict__ b1) {
    const size_t r1 = 20000u * 256 / 8;
    GS(i, (size_t)VHP * 256 / 8) {
        float4 a, b;
        if (i < r1) { a = W1[2 * i]; b = W1[2 * i + 1]; }
        else        { a = b = make_float4(0.f, 0.f, 0.f, 0.f); }
        ((uint4*)g_W1v)[i] = pack8_scaled(a, b);
        if (i < VHP) g_bb1[i] = __float2bfloat16(i < 20000 ? b1[i] * LOG2E : -30000.f);
    }
}

// ---------------- proj GEMM (3-stage pipelined): g_projb = g_hb @ g_pT^T ----------------
__global__ __launch_bounds__(256, 2)
void gemm_proj() {
    constexpr int BK = 64, LD = BK + 8, T = 16, R8 = BK / 8, BUF = 128 * LD, STG = 2 * BUF;
    extern __shared__ bf16 smem[];
    const int tid = threadIdx.x, warp = tid >> 5, lane = tid & 31;
    const int wm = warp >> 1, wn = warp & 1;
    const int nbase = blockIdx.x * 128, rb = blockIdx.y;
    float acc[2][8][4];
#pragma unroll
    for (int a = 0; a < 2; a++)
#pragma unroll
        for (int b = 0; b < 8; b++)
#pragma unroll
            for (int c = 0; c < 4; c++) acc[a][b][c] = 0.f;

    auto load = [&](int kt) {
        bf16* s = smem + (kt % 3) * STG;
        const bf16* As = g_hb + (size_t)(rb * 128) * 1024 + kt * BK;
        const bf16* Bs = g_pT + kt * BK;
#pragma unroll
        for (int i = tid; i < 128 * R8; i += 256) {
            int r = i / R8, c = i % R8;
            cpa16(s + r * LD + c * 8, As + (size_t)r * 1024 + c * 8);
            int wr = (nbase + r < PCOLS) ? nbase + r : PCOLS - 1;
            cpa16(s + BUF + r * LD + c * 8, Bs + (size_t)wr * 1024 + c * 8);
        }
        CP_COMMIT();
    };
    load(0); load(1);
    for (int kt = 0; kt < T; kt++) {
        if (kt < T - 1) asm volatile("cp.async.wait_group 1;");
        else            asm volatile("cp.async.wait_group 0;");
        __syncthreads();
        if (kt + 2 < T) load(kt + 2);
        const bf16* aB = smem + (kt % 3) * STG;
        const bf16* bB = aB + BUF;
#pragma unroll
        for (int ks = 0; ks < BK / 16; ks++) {
            unsigned afr[2][4];
#pragma unroll
            for (int mt = 0; mt < 2; mt++)
                ldsm_x4(afr[mt], aB + (wm * 32 + mt * 16 + (lane & 15)) * LD + ks * 16 + (lane >> 4) * 8);
#pragma unroll
            for (int np = 0; np < 4; np++) {
                unsigned bq[4];
                int g = lane >> 3;
                ldsm_x4(bq, bB + (wn * 64 + (np * 2 + (g >> 1)) * 8 + (lane & 7)) * LD + ks * 16 + (g & 1) * 8);
                mma16816(acc[0][np * 2],     afr[0], bq);
                mma16816(acc[1][np * 2],     afr[1], bq);
                mma16816(acc[0][np * 2 + 1], afr[0], bq + 2);
                mma16816(acc[1][np * 2 + 1], afr[1], bq + 2);
            }
        }
    }
#pragma unroll
    for (int mt = 0; mt < 2; mt++)
#pragma unroll
        for (int nt = 0; nt < 8; nt++)
#pragma unroll
            for (int k = 0; k < 4; k++) {
                int r = rb * 128 + wm * 32 + mt * 16 + (lane >> 2) + ((k >= 2) ? 8 : 0);
                int c = nbase + wn * 64 + nt * 8 + (lane & 3) * 2 + (k & 1);
                if (c < PCOLS) g_projb[(size_t)r * PCOLS + c] = __float2bfloat16(acc[mt][nt][k]);
            }
}

// ---------------- fused GEMM + per-tile sum(2^x): 2-stage (head K=1024 / tail1 K=256) ----------------
template <int K, int BK>
__global__ __launch_bounds__(256, 2)
void gemm_lse(int id, int proj_off, int NT) {
    constexpr int LD = BK + 8, T = K / BK, R8 = BK / 8, BUF = 128 * LD;
    extern __shared__ bf16 smem[];
    bf16* sA = smem;
    bf16* sB = smem + 2 * BUF;
    float* sRf = (float*)(smem + 4 * BUF);   // [128][2]

    const bf16* Wb = (id == 0) ? g_Wh  : g_W1v;
    const bf16* bb = (id == 0) ? g_bbh : g_bb1;
    float* part    = (id == 0) ? g_partH : g_part1;

    const int tid = threadIdx.x, warp = tid >> 5, lane = tid & 31;
    const int wm = warp >> 1, wn = warp & 1;
    const int vt = blockIdx.x, rb = blockIdx.y;
    const int vbase = vt * 128;
    const bf16* Ab = g_projb + (size_t)(rb * 128) * PCOLS + proj_off;

    unsigned bpre[8];
#pragma unroll
    for (int nt = 0; nt < 8; nt++)
        bpre[nt] = *(const unsigned*)(bb + (vbase + wn * 64 + nt * 8 + (lane & 3) * 2));

    float acc[2][8][4];
#pragma unroll
    for (int a = 0; a < 2; a++)
#pragma unroll
        for (int b = 0; b < 8; b++)
#pragma unroll
            for (int c = 0; c < 4; c++) acc[a][b][c] = 0.f;

    auto load = [&](int kt, int buf) {
        const bf16* As = Ab + kt * BK;
        const bf16* Bs = Wb + (size_t)vbase * K + kt * BK;
#pragma unroll
        for (int i = tid; i < 128 * R8; i += 256) {
            int r = i / R8, c = i % R8;
            cpa16(sA + buf * BUF + r * LD + c * 8, As + (size_t)r * PCOLS + c * 8);
            cpa16(sB + buf * BUF + r * LD + c * 8, Bs + (size_t)r * K + c * 8);
        }
        CP_COMMIT();
    };
    load(0, 0);
    for (int kt = 0; kt < T; kt++) {
        int buf = kt & 1;
        if (kt + 1 < T) { load(kt + 1, buf ^ 1); asm volatile("cp.async.wait_group 1;"); }
        else            { asm volatile("cp.async.wait_group 0;"); }
        __syncthreads();
        const bf16* aB = sA + buf * BUF;
        const bf16* bB = sB + buf * BUF;
#pragma unroll
        for (int ks = 0; ks < BK / 16; ks++) {
            unsigned afr[2][4];
#pragma unroll
            for (int mt = 0; mt < 2; mt++)
                ldsm_x4(afr[mt], aB + (wm * 32 + mt * 16 + (lane & 15)) * LD + ks * 16 + (lane >> 4) * 8);
#pragma unroll
            for (int np = 0; np < 4; np++) {
                unsigned bq[4];
                int g = lane >> 3;
                ldsm_x4(bq, bB + (wn * 64 + (np * 2 + (g >> 1)) * 8 + (lane & 7)) * LD + ks * 16 + (g & 1) * 8);
                mma16816(acc[0][np * 2],     afr[0], bq);
                mma16816(acc[1][np * 2],     afr[1], bq);
                mma16816(acc[0][np * 2 + 1], afr[0], bq + 2);
                mma16816(acc[1][np * 2 + 1], afr[1], bq + 2);
            }
        }
        __syncthreads();
    }
    // epilogue: s = sum 2^(logit' + bias')
#pragma unroll
    for (int mt = 0; mt < 2; mt++)
#pragma unroll
        for (int rr = 0; rr < 2; rr++) {
            float s0 = 0.f, s1 = 0.f;
#pragma unroll
            for (int nt = 0; nt < 8; nt++) {
                float a0 = acc[mt][nt][rr * 2], a1 = acc[mt][nt][rr * 2 + 1];
                unsigned lp, lb, e;
                asm("cvt.rn.bf16x2.f32 %0, %1, %2;" : "=r"(lp) : "f"(a1), "f"(a0));
                asm("fma.rn.bf16x2 %0, %1, %2, %3;" : "=r"(lb) : "r"(lp), "r"(0x3F803F80u), "r"(bpre[nt]));
                asm("ex2.approx.ftz.bf16x2 %0, %1;" : "=r"(e) : "r"(lb));
                s0 += __uint_as_float(e << 16);
                s1 += __uint_as_float(e & 0xFFFF0000u);
            }
            float s = s0 + s1;
            s += __shfl_xor_sync(0xffffffffu, s, 1);
            s += __shfl_xor_sync(0xffffffffu, s, 2);
            if ((lane & 3) == 0)
                sRf[(wm * 32 + mt * 16 + rr * 8 + (lane >> 2)) * 2 + wn] = s;
        }
    __syncthreads();
    if (tid < 128)
        part[(size_t)(rb * 128 + tid) * NT + vt] = sRf[tid * 2] + sRf[tid * 2 + 1];
}

// ---------------- tail GEMM+LSE: fp32 W converted in-kernel, B resident (K = 64 / 16) ----------------
template <int K>
__global__ __launch_bounds__(256, 2)
void gemm_lse_tail(const float* __restrict__ W, const float* __restrict__ bias,
                   int proj_off, int NT, int V) {
    constexpr int LD = K + 8, R8 = K / 8, ABUF = 128 * LD;
    extern __shared__ bf16 smem[];
    bf16* sA = smem;               // 2 buffers
    bf16* sB = smem + 2 * ABUF;    // resident B (converted from fp32 here)
    float* sRf = (float*)(smem + 3 * ABUF);
    float* part = (K == 64) ? g_part2 : g_part3;

    const int tid = threadIdx.x, warp = tid >> 5, lane = tid & 31;
    const int wm = warp >> 1, wn = warp & 1;
    const int vt = blockIdx.x;
    const int vbase = vt * 128;

    // bias: load fp32, scale, pack to bf16x2 (pad -> -30000 => 2^x = 0)
    unsigned bpre[8];
#pragma unroll
    for (int nt = 0; nt < 8; nt++) {
        int col = vbase + wn * 64 + nt * 8 + (lane & 3) * 2;
        float f0 = (col     < V) ? bias[col]     * LOG2E : -30000.f;
        float f1 = (col + 1 < V) ? bias[col + 1] * LOG2E : -30000.f;
        bf162 p = __floats2bfloat162_rn(f0, f1);
        bpre[nt] = *(unsigned*)&p;
    }

    // A(rb=0) via cp.async
    {
        const bf16* As = g_projb + proj_off;
#pragma unroll
        for (int i = tid; i < 128 * R8; i += 256) {
            int r = i / R8, c = i % R8;
            cpa16(sA + r * LD + c * 8, As + (size_t)r * PCOLS + c * 8);
        }
        CP_COMMIT();
    }
    // resident B: fp32 -> bf16*log2e, direct from input weights (read exactly once)
    {
        constexpr int UN = 128 * K / 8;
#pragma unroll
        for (int u = tid; u < UN; u += 256) {
            int r = u / (K / 8), cc = u % (K / 8);
            int row = vbase + r; if (row >= V) row = V - 1;
            const float4* Wf = (const float4*)(W + (size_t)row * K + cc * 8);
            *(uint4*)(sB + r * LD + cc * 8) = pack8_scaled(Wf[0], Wf[1]);
        }
    }
    for (int rb = 0; rb < 8; rb++) {
        int buf = rb & 1;
        if (rb + 1 < 8) {
            const bf16* As = g_projb + (size_t)((rb + 1) * 128) * PCOLS + proj_off;
#pragma unroll
            for (int i = tid; i < 128 * R8; i += 256) {
                int r = i / R8, c = i % R8;
                cpa16(sA + (buf ^ 1) * ABUF + r * LD + c * 8, As + (size_t)r * PCOLS + c * 8);
            }
            CP_COMMIT();
            asm volatile("cp.async.wait_group 1;");
        } else {
            asm volatile("cp.async.wait_group 0;");
        }
        __syncthreads();
        const bf16* aB = sA + buf * ABUF;
        float acc[2][8][4];
#pragma unroll
        for (int a = 0; a < 2; a++)
#pragma unroll
            for (int b = 0; b < 8; b++)
#pragma unroll
                for (int c = 0; c < 4; c++) acc[a][b][c] = 0.f;
#pragma unroll
        for (int ks = 0; ks < K / 16; ks++) {
            unsigned afr[2][4];
#pragma unroll
            for (int mt = 0; mt < 2; mt++)
                ldsm_x4(afr[mt], aB + (wm * 32 + mt * 16 + (lane & 15)) * LD + ks * 16 + (lane >> 4) * 8);
#pragma unroll
            for (int np = 0; np < 4; np++) {
                unsigned bq[4];
                int g = lane >> 3;
                ldsm_x4(bq, sB + (wn * 64 + (np * 2 + (g >> 1)) * 8 + (lane & 7)) * LD + ks * 16 + (g & 1) * 8);
                mma16816(acc[0][np * 2],     afr[0], bq);
                mma16816(acc[1][np * 2],     afr[1], bq);
                mma16816(acc[0][np * 2 + 1], afr[0], bq + 2);
                mma16816(acc[1][np * 2 + 1], afr[1], bq + 2);
            }
        }
#pragma unroll
        for (int mt = 0; mt < 2; mt++)
#pragma unroll
            for (int rr = 0; rr < 2; rr++) {
                float s0 = 0.f, s1 = 0.f;
#pragma unroll
                for (int nt = 0; nt < 8; nt++) {
                    float a0 = acc[mt][nt][rr * 2], a1 = acc[mt][nt][rr * 2 + 1];
                    unsigned lp, lb, e;
                    asm("cvt.rn.bf16x2.f32 %0, %1, %2;" : "=r"(lp) : "f"(a1), "f"(a0));
                    asm("fma.rn.bf16x2 %0, %1, %2, %3;" : "=r"(lb) : "r"(lp), "r"(0x3F803F80u), "r"(bpre[nt]));
                    asm("ex2.approx.ftz.bf16x2 %0, %1;" : "=r"(e) : "r"(lb));
                    s0 += __uint_as_float(e << 16);
                    s1 += __uint_as_float(e & 0xFFFF0000u);
                }
                float s = s0 + s1;
                s += __shfl_xor_sync(0xffffffffu, s, 1);
                s += __shfl_xor_sync(0xffffffffu, s, 2);
                if ((lane & 3) == 0)
                    sRf[(wm * 32 + mt * 16 + rr * 8 + (lane >> 2)) * 2 + wn] = s;
            }
        __syncthreads();
        if (tid < 128)
            part[(size_t)(rb * 128 + tid) * NT + vt] = sRf[tid * 2] + sRf[tid * 2 + 1];
        __syncthreads();
    }
}

// ---------------- final: combine partials + target logits ----------------
__device__ __forceinline__ float warp_sum(float x) {
#pragma unroll
    for (int d = 16; d; d >>= 1) x += __shfl_xor_sync(0xffffffffu, x, d);
    return x;
}
__device__ __forceinline__ float warp_lse(const float* part, int nt, int row, int lane) {
    float s = 0.f;
    for (int i = lane; i < nt; i += 32) s += part[(size_t)row * nt + i];
    return __logf(warp_sum(s));
}

__global__ __launch_bounds__(256)
void final_kernel(const unsigned* __restrict__ tgt,
                  const float* __restrict__ W0, const float* __restrict__ b0,
                  const float* __restrict__ W1, const float* __restrict__ b1,
                  const float* __restrict__ W2, const float* __restrict__ b2,
                  const float* __restrict__ W3, const float* __restrict__ b3,
                  const float* __restrict__ cw, const float* __restrict__ cb,
                  float* __restrict__ out) {
    const int warp = threadIdx.x >> 5, lane = threadIdx.x & 31;
    const int row = blockIdx.x * 8 + warp;
    if (row >= 1024) return;
    unsigned odd = tgt[1] | tgt[3] | tgt[5] | tgt[7] | tgt[9] | tgt[11] | tgt[13] | tgt[15];
    bool is64 = (odd == 0u);
    int t = (int)(is64 ? tgt[2 * row] : tgt[row]);

    float lseH = warp_lse(g_partH, 157, row, lane);
    const bf16* pr = g_projb + (size_t)row * PCOLS;
    float nll;
    if (t < 19997) {
        float d = 0.f;
        for (int k = lane; k < 1024; k += 32)
            d += __bfloat162float(pr[k]) * W0[(size_t)t * 1024 + k];
        d = warp_sum(d);
        nll = lseH - (d + b0[t]);
    } else {
        int ci, loff, Kc, ntc, poff;
        const float *Wt, *bt;
        const float* part;
        if (t < 39997)       { ci = 0; loff = 19997;  Kc = 256; ntc = 157;  poff = 1024; Wt = W1; bt = b1; part = g_part1; }
        else if (t < 199997) { ci = 1; loff = 39997;  Kc = 64;  ntc = 1250; poff = 1280; Wt = W2; bt = b2; part = g_part2; }
        else                 { ci = 2; loff = 199997; Kc = 16;  ntc = 530;  poff = 1344; Wt = W3; bt = b3; part = g_part3; }
        float lseT = warp_lse(part, ntc, row, lane);
        float dc = 0.f;
        for (int k = lane; k < 1024; k += 32)
            dc += __bfloat162float(pr[k]) * cw[(size_t)ci * 1024 + k];
        dc = warp_sum(dc);
        int rel = t - loff;
        float dt = 0.f;
        for (int k = lane; k < Kc; k += 32)
            dt += __bfloat162float(pr[poff + k]) * Wt[(size_t)rel * Kc + k];
        dt = warp_sum(dt);
        nll = (lseH - (dc + cb[ci])) + (lseT - (dt + bt[rel]));
    }
    if (lane == 0) out[row] = nll;
}

// ---------------- launch (multi-stream overlap, graph-capture safe) ----------------
struct AuxStreams {
    cudaStream_t s1, s2;
    cudaEvent_t eRoot, eHead, eW1, eProj, eSide;
    AuxStreams() {
        cudaStreamCreateWithFlags(&s1, cudaStreamNonBlocking);
        cudaStreamCreateWithFlags(&s2, cudaStreamNonBlocking);
        cudaEventCreateWithFlags(&eRoot, cudaEventDisableTiming);
        cudaEventCreateWithFlags(&eHead, cudaEventDisableTiming);
        cudaEventCreateWithFlags(&eW1,   cudaEventDisableTiming);
        cudaEventCreateWithFlags(&eProj, cudaEventDisableTiming);
        cudaEventCreateWithFlags(&eSide, cudaEventDisableTiming);
    }
};
static AuxStreams& aux() { static AuxStreams a; return a; }

extern "C" void kernel_launch(void* const* d_in, const int* in_sizes, int n_in,
                              void* d_out, int out_size) {
    const float*    hidden = (const float*)d_in[0];
    const unsigned* target = (const unsigned*)d_in[1];
    const float* W0 = (const float*)d_in[2],  *b0 = (const float*)d_in[3],  *p0 = (const float*)d_in[4];
    const float* W1 = (const float*)d_in[5],  *b1 = (const float*)d_in[6],  *p1 = (const float*)d_in[7];
    const float* W2 = (const float*)d_in[8],  *b2 = (const float*)d_in[9],  *p2 = (const float*)d_in[10];
    const float* W3 = (const float*)d_in[11], *b3 = (const float*)d_in[12], *p3 = (const float*)d_in[13];
    const float* cw = (const float*)d_in[14], *cb = (const float*)d_in[15];
    float* out = (float*)d_out;
    AuxStreams& ax = aux();

    const int SM2   = 4 * 128 * 72 * 2 + 128 * 2 * 4;   // 74752 B (2-stage A+B + sRf)
    const int SMPJ  = 3 * (2 * 128 * 72) * 2;           // 110592 B (3-stage)
    const int SMT64 = 3 * 128 * 72 * 2 + 128 * 2 * 4;   // 56320 B
    const int SMT16 = 3 * 128 * 24 * 2 + 128 * 2 * 4;   // 19456 B
    cudaFuncSetAttribute(gemm_proj,         cudaFuncAttributeMaxDynamicSharedMemorySize, SMPJ);
    cudaFuncSetAttribute(gemm_lse<1024,64>, cudaFuncAttributeMaxDynamicSharedMemorySize, SM2);
    cudaFuncSetAttribute(gemm_lse<256,64>,  cudaFuncAttributeMaxDynamicSharedMemorySize, SM2);
    cudaFuncSetAttribute(gemm_lse_tail<64>, cudaFuncAttributeMaxDynamicSharedMemorySize, SMT64);
    cudaFuncSetAttribute(gemm_lse_tail<16>, cudaFuncAttributeMaxDynamicSharedMemorySize, SMT16);

    cudaEventRecord(ax.eRoot, 0);

    // main stream: hidden/proj conversion -> proj GEMM
    k_convHP<<<1888, 256>>>((const float4*)hidden, p0, p1, p2, p3);                    // #0
    // side stream 1: head weight conversion (overlaps convHP + proj)
    cudaStreamWaitEvent(ax.s1, ax.eRoot, 0);
    k_convHead<<<8192, 256, 0, ax.s1>>>((const float4*)W0, (const float4*)cw, b0, cb); // #1
    cudaEventRecord(ax.eHead, ax.s1);

    gemm_proj<<<dim3(11, 8), 256, SMPJ>>>();                                           // #2
    cudaEventRecord(ax.eProj, 0);

    // head GEMM (needs convHead + proj), 2-stage -> 74.7KB/CTA leaves smem for tail co-residency
    cudaStreamWaitEvent(0, ax.eHead, 0);
    gemm_lse<1024, 64><<<dim3(157, 8), 256, SM2>>>(0, 0, 157);                         // #3 <- profile me

    // side stream 1 continues: W1 conversion (overlaps head)
    k_convW1<<<2560, 256, 0, ax.s1>>>((const float4*)W1, b1);                          // #4
    cudaEventRecord(ax.eW1, ax.s1);

    // side stream 2: tail2/3 need only proj (W2/W3 converted in-kernel); fill head's gaps
    cudaStreamWaitEvent(ax.s2, ax.eProj, 0);
    gemm_lse_tail<64><<<1250, 256, SMT64, ax.s2>>>(W2, b2, 1280, 1250, 160000);        // #5
    gemm_lse_tail<16><<<530,  256, SMT16, ax.s2>>>(W3, b3, 1344, 530, 67738);          // #6
    cudaEventRecord(ax.eSide, ax.s2);

    // main stream: tail1 GEMM (needs convW1), then final join
    cudaStreamWaitEvent(0, ax.eW1, 0);
    gemm_lse<256, 64><<<dim3(157, 8), 256, SM2>>>(1, 1024, 157);                       // #7
    cudaStreamWaitEvent(0, ax.eSide, 0);
    final_kernel<<<128, 256>>>(target, W0, b0, W1, b1, W2, b2, W3, b3, cw, cb, out);   // #8
}